// round 1
// baseline (speedup 1.0000x reference)
#include <cuda_runtime.h>
#include <math.h>

#define TOKENS 4096
#define HID    4096
#define NHEADS 32
#define NKVH   8
#define HDIM   128
#define SEQ    1024
#define QKV_LD 6144   // q(4096) | k(1024) | v(1024)

// Scratch (allocation-free rule: __device__ globals)
__device__ float g_qkv[TOKENS * QKV_LD];   // ~100.7 MB
__device__ float g_attn[TOKENS * HID];     // ~67.1 MB

// ---------------------------------------------------------------------------
// SGEMM NT: C[M,N] = A[M,K] * B[N,K]^T   (A,B row-major, K-contiguous)
// 128x128 tile, BK=8, 8x8 per thread, 256 threads
// ---------------------------------------------------------------------------
__global__ __launch_bounds__(256)
void sgemm_nt(const float* __restrict__ A, const float* __restrict__ B,
              float* __restrict__ C, int M, int N, int K,
              int lda, int ldb, int ldc) {
    __shared__ float As[8][132];
    __shared__ float Bs[8][132];

    const int bm = blockIdx.y * 128;
    const int bn = blockIdx.x * 128;
    const int tid = threadIdx.x;
    const int tx = tid & 15;
    const int ty = tid >> 4;
    const int lr = tid >> 1;          // 0..127 tile row to load
    const int lc = (tid & 1) * 4;     // 0 or 4 within BK

    const float* Ap = A + (size_t)(bm + lr) * lda + lc;
    const float* Bp = B + (size_t)(bn + lr) * ldb + lc;

    float acc[8][8];
#pragma unroll
    for (int i = 0; i < 8; i++)
#pragma unroll
        for (int j = 0; j < 8; j++) acc[i][j] = 0.f;

    for (int k0 = 0; k0 < K; k0 += 8) {
        float4 av = *(const float4*)(Ap + k0);
        float4 bv = *(const float4*)(Bp + k0);
        As[lc + 0][lr] = av.x; As[lc + 1][lr] = av.y;
        As[lc + 2][lr] = av.z; As[lc + 3][lr] = av.w;
        Bs[lc + 0][lr] = bv.x; Bs[lc + 1][lr] = bv.y;
        Bs[lc + 2][lr] = bv.z; Bs[lc + 3][lr] = bv.w;
        __syncthreads();

#pragma unroll
        for (int kk = 0; kk < 8; kk++) {
            float4 a0 = *(const float4*)(&As[kk][ty * 8]);
            float4 a1 = *(const float4*)(&As[kk][ty * 8 + 4]);
            float4 b0 = *(const float4*)(&Bs[kk][tx * 8]);
            float4 b1 = *(const float4*)(&Bs[kk][tx * 8 + 4]);
            float a[8] = {a0.x, a0.y, a0.z, a0.w, a1.x, a1.y, a1.z, a1.w};
            float b[8] = {b0.x, b0.y, b0.z, b0.w, b1.x, b1.y, b1.z, b1.w};
#pragma unroll
            for (int i = 0; i < 8; i++)
#pragma unroll
                for (int j = 0; j < 8; j++) acc[i][j] += a[i] * b[j];
        }
        __syncthreads();
    }

#pragma unroll
    for (int i = 0; i < 8; i++) {
        float* cp = C + (size_t)(bm + ty * 8 + i) * ldc + bn + tx * 8;
        float4 v0 = make_float4(acc[i][0], acc[i][1], acc[i][2], acc[i][3]);
        float4 v1 = make_float4(acc[i][4], acc[i][5], acc[i][6], acc[i][7]);
        *(float4*)(cp) = v0;
        *(float4*)(cp + 4) = v1;
    }
}

// ---------------------------------------------------------------------------
// RoPE in-place on q (heads 0..31) and k (heads 32..39) of g_qkv.
// Pair (d, d+64), freq index d//2 (repeat_interleave of 64 freqs).
// ---------------------------------------------------------------------------
__global__ void rope_kernel(float* __restrict__ qkv,
                            const int* __restrict__ positions) {
    int idx = blockIdx.x * blockDim.x + threadIdx.x;
    const int total = TOKENS * (NHEADS + NKVH) * 64;
    if (idx >= total) return;
    int d = idx & 63;
    int rest = idx >> 6;
    int head = rest % (NHEADS + NKVH);
    int t = rest / (NHEADS + NKVH);

    int pos = positions[t];
    pos = pos < 0 ? 0 : (pos > SEQ - 1 ? SEQ - 1 : pos);

    float* base = qkv + (size_t)t * QKV_LD +
                  (head < NHEADS ? head * HDIM : HID + (head - NHEADS) * HDIM);
    float x1 = base[d];
    float x2 = base[d + 64];

    const float LC = 0.14391156831212875f;   // ln(10000)/64
    int j1 = d >> 1;
    float f1 = expf(-(float)j1 * LC);
    float f2 = expf(-(float)(j1 + 32) * LC);
    float p = (float)pos;
    float s1, c1, s2, c2;
    sincosf(p * f1, &s1, &c1);
    sincosf(p * f2, &s2, &c2);

    base[d]      = x1 * c1 - x2 * s1;
    base[d + 64] = x2 * c2 + x1 * s2;
}

// ---------------------------------------------------------------------------
// Flash attention (fp32, causal, GQA). Block: 64 queries x full HD=128.
// 256 threads: (ty,tx) = 16x16; scores 4x4 micro-tile; O rows ty*4+i,
// cols [tx*4, tx*4+4) and [64+tx*4, 64+tx*4+4).
// Q/K tiles stored as float4 with an XOR swizzle on the 8 bank-groups.
// ---------------------------------------------------------------------------
#define ATT_SMEM ((3 * 64 * 128 + 64 * 65) * 4)

__device__ __forceinline__ int swz(int row, int k4) {
    return row * 32 + ((k4 & 24) | ((k4 ^ (row >> 2)) & 7));
}

__global__ __launch_bounds__(256)
void attn_kernel(const float* __restrict__ qkv, float* __restrict__ aout) {
    extern __shared__ float smem[];
    float4* Qs = (float4*)smem;          // 64 rows x 32 float4 (swizzled)
    float4* Ks = Qs + 64 * 32;           // same
    float4* Vs = Ks + 64 * 32;           // 64 rows x 32 float4 (plain)
    float*  Ps = (float*)(Vs + 64 * 32); // [64][65]

    const int qb = blockIdx.x;
    const int h  = blockIdx.y;
    const int b  = blockIdx.z;
    const int kvh = h >> 2;              // repeat_interleave(4)
    const int tid = threadIdx.x;
    const int tx = tid & 15;
    const int ty = tid >> 4;
    const int q0 = qb * 64;
    const size_t tok0 = (size_t)b * SEQ;

    // Load Q tile (swizzled)
    const float* qbase = qkv + (tok0 + q0) * QKV_LD + h * HDIM;
    for (int u = tid; u < 64 * 32; u += 256) {
        int r = u >> 5, k4 = u & 31;
        Qs[swz(r, k4)] = *(const float4*)(qbase + (size_t)r * QKV_LD + k4 * 4);
    }

    float m[4], l[4], o[4][8];
#pragma unroll
    for (int i = 0; i < 4; i++) {
        m[i] = -INFINITY; l[i] = 0.f;
#pragma unroll
        for (int j = 0; j < 8; j++) o[i][j] = 0.f;
    }

    const float* kbase = qkv + tok0 * QKV_LD + HID + kvh * HDIM;
    const float* vbase = kbase + NKVH * HDIM;

    for (int kb = 0; kb <= qb; kb++) {
        const int k0 = kb * 64;
        __syncthreads();   // previous PV readers done before overwrite
        for (int u = tid; u < 64 * 32; u += 256) {
            int r = u >> 5, k4 = u & 31;
            size_t roff = (size_t)(k0 + r) * QKV_LD + (size_t)k4 * 4;
            Ks[swz(r, k4)] = *(const float4*)(kbase + roff);
            Vs[u]          = *(const float4*)(vbase + roff);
        }
        __syncthreads();

        // S = Q K^T (4x4 per thread)
        float s[4][4];
#pragma unroll
        for (int i = 0; i < 4; i++)
#pragma unroll
            for (int j = 0; j < 4; j++) s[i][j] = 0.f;

#pragma unroll 4
        for (int k4 = 0; k4 < 32; k4++) {
            float4 qv[4], kv[4];
#pragma unroll
            for (int i = 0; i < 4; i++)
                qv[i] = Qs[(ty * 4 + i) * 32 + ((k4 & 24) | ((k4 ^ ty) & 7))];
#pragma unroll
            for (int j = 0; j < 4; j++)
                kv[j] = Ks[(tx * 4 + j) * 32 + ((k4 & 24) | ((k4 ^ tx) & 7))];
#pragma unroll
            for (int i = 0; i < 4; i++)
#pragma unroll
                for (int j = 0; j < 4; j++)
                    s[i][j] += qv[i].x * kv[j].x + qv[i].y * kv[j].y +
                               qv[i].z * kv[j].z + qv[i].w * kv[j].w;
        }

        // online softmax
        const float sc = 0.08838834764831845f;  // 1/sqrt(128)
#pragma unroll
        for (int i = 0; i < 4; i++) {
            const int qpos = q0 + ty * 4 + i;
            float rowm = -INFINITY;
#pragma unroll
            for (int j = 0; j < 4; j++) {
                float v = s[i][j] * sc;
                if (k0 + tx * 4 + j > qpos) v = -INFINITY;
                s[i][j] = v;
                rowm = fmaxf(rowm, v);
            }
#pragma unroll
            for (int off = 8; off; off >>= 1)
                rowm = fmaxf(rowm, __shfl_xor_sync(0xffffffffu, rowm, off));
            float nm = fmaxf(m[i], rowm);
            float corr = expf(m[i] - nm);
            float rs = 0.f;
#pragma unroll
            for (int j = 0; j < 4; j++) {
                float p = expf(s[i][j] - nm);
                Ps[(ty * 4 + i) * 65 + tx * 4 + j] = p;
                rs += p;
            }
#pragma unroll
            for (int off = 8; off; off >>= 1)
                rs += __shfl_xor_sync(0xffffffffu, rs, off);
            l[i] = l[i] * corr + rs;
            m[i] = nm;
#pragma unroll
            for (int j = 0; j < 8; j++) o[i][j] *= corr;
        }
        __syncthreads();

        // O += P V
#pragma unroll 4
        for (int kk = 0; kk < 64; kk++) {
            float4 v1 = Vs[kk * 32 + tx];
            float4 v2 = Vs[kk * 32 + 16 + tx];
#pragma unroll
            for (int i = 0; i < 4; i++) {
                float p = Ps[(ty * 4 + i) * 65 + kk];
                o[i][0] += p * v1.x; o[i][1] += p * v1.y;
                o[i][2] += p * v1.z; o[i][3] += p * v1.w;
                o[i][4] += p * v2.x; o[i][5] += p * v2.y;
                o[i][6] += p * v2.z; o[i][7] += p * v2.w;
            }
        }
    }

    float* ob = aout + (tok0 + q0) * HID + h * HDIM;
#pragma unroll
    for (int i = 0; i < 4; i++) {
        int r = ty * 4 + i;
        float inv = 1.0f / l[i];
        float4 w1 = make_float4(o[i][0] * inv, o[i][1] * inv,
                                o[i][2] * inv, o[i][3] * inv);
        float4 w2 = make_float4(o[i][4] * inv, o[i][5] * inv,
                                o[i][6] * inv, o[i][7] * inv);
        *(float4*)(ob + (size_t)r * HID + tx * 4) = w1;
        *(float4*)(ob + (size_t)r * HID + 64 + tx * 4) = w2;
    }
}

// ---------------------------------------------------------------------------
// Launch: QKV gemms -> RoPE -> attention -> output gemm
// Inputs: 0:x 1:positions 2:kv_cache 3:wq 4:wk 5:wv 6:wo 7:seq_len
// ---------------------------------------------------------------------------
extern "C" void kernel_launch(void* const* d_in, const int* in_sizes, int n_in,
                              void* d_out, int out_size) {
    const float* x         = (const float*)d_in[0];
    const int*   positions = (const int*)d_in[1];
    const float* wq        = (const float*)d_in[3];
    const float* wk        = (const float*)d_in[4];
    const float* wv        = (const float*)d_in[5];
    const float* wo        = (const float*)d_in[6];
    float* out = (float*)d_out;

    float *qkv = nullptr, *attn = nullptr;
    cudaGetSymbolAddress((void**)&qkv, g_qkv);
    cudaGetSymbolAddress((void**)&attn, g_attn);

    dim3 blk(256);
    // QKV projections (C = x @ W^T) into packed qkv buffer
    sgemm_nt<<<dim3(32, 32), blk>>>(x, wq, qkv,        TOKENS, 4096, HID, HID, HID, QKV_LD);
    sgemm_nt<<<dim3(8,  32), blk>>>(x, wk, qkv + 4096, TOKENS, 1024, HID, HID, HID, QKV_LD);
    sgemm_nt<<<dim3(8,  32), blk>>>(x, wv, qkv + 5120, TOKENS, 1024, HID, HID, HID, QKV_LD);

    // RoPE on q and k
    rope_kernel<<<(TOKENS * 40 * 64 + 255) / 256, 256>>>(qkv, positions);

    // Flash attention
    cudaFuncSetAttribute(attn_kernel, cudaFuncAttributeMaxDynamicSharedMemorySize, ATT_SMEM);
    attn_kernel<<<dim3(SEQ / 64, NHEADS, TOKENS / SEQ), blk, ATT_SMEM>>>(qkv, attn);

    // Output projection
    sgemm_nt<<<dim3(32, 32), blk>>>(attn, wo, out, TOKENS, HID, HID, HID, HID, HID);
}

// round 2
// speedup vs baseline: 2.1616x; 2.1616x over previous
#include <cuda_runtime.h>
#include <math.h>

#define TOKENS 4096
#define HID    4096
#define NHEADS 32
#define NKVH   8
#define HDIM   128
#define SEQ    1024
#define QKV_LD 6144   // q(4096) | k(1024) | v(1024)

// Scratch (allocation-free rule: __device__ globals)
__device__ float g_qkv[TOKENS * QKV_LD];
__device__ float g_attn[TOKENS * HID];

// ---------------------------------------------------------------------------
// TF32 helpers
// ---------------------------------------------------------------------------
__device__ __forceinline__ unsigned f2tf(float x) {
    unsigned r;
    asm("cvt.rna.tf32.f32 %0, %1;" : "=r"(r) : "f"(x));
    return r;
}

__device__ __forceinline__ void mma_tf32(float c[4],
    unsigned a0, unsigned a1, unsigned a2, unsigned a3,
    unsigned b0, unsigned b1) {
    asm volatile(
        "mma.sync.aligned.m16n8k8.row.col.f32.tf32.tf32.f32 "
        "{%0,%1,%2,%3}, {%4,%5,%6,%7}, {%8,%9}, {%0,%1,%2,%3};"
        : "+f"(c[0]), "+f"(c[1]), "+f"(c[2]), "+f"(c[3])
        : "r"(a0), "r"(a1), "r"(a2), "r"(a3), "r"(b0), "r"(b1));
}

// ---------------------------------------------------------------------------
// TF32 tensor-core GEMM body: C[bm:bm+128, 0:128] += A[M,K] * Bt[128,K]^T
// A row-major (lda), Bt row-major (ldb, 128 rows of the N tile), C (ldc).
// 256 threads, 8 warps (2x4), warp tile 64x32, BK=16, double-buffered smem.
// Smem row stride 20 -> fragment gathers and stores are bank-conflict-free.
// ---------------------------------------------------------------------------
#define SST 20

__device__ __forceinline__ void gemm128(
    const float* __restrict__ A, const float* __restrict__ Bt,
    float* __restrict__ C, int K, int lda, int ldb, int ldc, int bm)
{
    __shared__ unsigned As[2][128 * SST];
    __shared__ unsigned Bs[2][128 * SST];

    const int tid  = threadIdx.x;
    const int lrow = tid >> 1;          // 0..127 : tile row to load
    const int lc8  = (tid & 1) * 8;     // 0 or 8 : k offset within BK=16
    const int wid  = tid >> 5;
    const int lane = tid & 31;
    const int g    = lane >> 2;         // group id 0..7
    const int t    = lane & 3;          // thread-in-group 0..3
    const int wm   = (wid & 1) * 64;    // warp m offset
    const int wn   = (wid >> 1) * 32;   // warp n offset

    const float* Ap = A  + (size_t)(bm + lrow) * lda + lc8;
    const float* Bp = Bt + (size_t)lrow * ldb + lc8;

    float acc[4][4][4];
#pragma unroll
    for (int i = 0; i < 4; i++)
#pragma unroll
        for (int j = 0; j < 4; j++)
#pragma unroll
            for (int r = 0; r < 4; r++) acc[i][j][r] = 0.f;

    // Prefetch first tile
    float4 ra0 = *(const float4*)(Ap);
    float4 ra1 = *(const float4*)(Ap + 4);
    float4 rb0 = *(const float4*)(Bp);
    float4 rb1 = *(const float4*)(Bp + 4);

    {   // store tile 0 into buffer 0 (tf32-converted)
        unsigned* as = As[0] + lrow * SST + lc8;
        as[0] = f2tf(ra0.x); as[1] = f2tf(ra0.y); as[2] = f2tf(ra0.z); as[3] = f2tf(ra0.w);
        as[4] = f2tf(ra1.x); as[5] = f2tf(ra1.y); as[6] = f2tf(ra1.z); as[7] = f2tf(ra1.w);
        unsigned* bs = Bs[0] + lrow * SST + lc8;
        bs[0] = f2tf(rb0.x); bs[1] = f2tf(rb0.y); bs[2] = f2tf(rb0.z); bs[3] = f2tf(rb0.w);
        bs[4] = f2tf(rb1.x); bs[5] = f2tf(rb1.y); bs[6] = f2tf(rb1.z); bs[7] = f2tf(rb1.w);
    }
    __syncthreads();

    int buf = 0;
    for (int k0 = 0; k0 < K; k0 += 16) {
        const bool has_next = (k0 + 16) < K;
        if (has_next) {   // issue LDG early; ~full iteration of HMMA covers latency
            ra0 = *(const float4*)(Ap + k0 + 16);
            ra1 = *(const float4*)(Ap + k0 + 20);
            rb0 = *(const float4*)(Bp + k0 + 16);
            rb1 = *(const float4*)(Bp + k0 + 20);
        }

        const unsigned* as = As[buf];
        const unsigned* bs = Bs[buf];
#pragma unroll
        for (int ks = 0; ks < 2; ks++) {
            const int kb = ks * 8;
            unsigned af[4][4], bf[4][2];
#pragma unroll
            for (int mi = 0; mi < 4; mi++) {
                const unsigned* ap = as + (wm + mi * 16 + g) * SST + kb + t;
                af[mi][0] = ap[0];
                af[mi][1] = ap[8 * SST];
                af[mi][2] = ap[4];
                af[mi][3] = ap[8 * SST + 4];
            }
#pragma unroll
            for (int ni = 0; ni < 4; ni++) {
                const unsigned* bp = bs + (wn + ni * 8 + g) * SST + kb + t;
                bf[ni][0] = bp[0];
                bf[ni][1] = bp[4];
            }
#pragma unroll
            for (int mi = 0; mi < 4; mi++)
#pragma unroll
                for (int ni = 0; ni < 4; ni++)
                    mma_tf32(acc[mi][ni], af[mi][0], af[mi][1], af[mi][2], af[mi][3],
                             bf[ni][0], bf[ni][1]);
        }

        if (has_next) {
            unsigned* asw = As[buf ^ 1] + lrow * SST + lc8;
            asw[0] = f2tf(ra0.x); asw[1] = f2tf(ra0.y); asw[2] = f2tf(ra0.z); asw[3] = f2tf(ra0.w);
            asw[4] = f2tf(ra1.x); asw[5] = f2tf(ra1.y); asw[6] = f2tf(ra1.z); asw[7] = f2tf(ra1.w);
            unsigned* bsw = Bs[buf ^ 1] + lrow * SST + lc8;
            bsw[0] = f2tf(rb0.x); bsw[1] = f2tf(rb0.y); bsw[2] = f2tf(rb0.z); bsw[3] = f2tf(rb0.w);
            bsw[4] = f2tf(rb1.x); bsw[5] = f2tf(rb1.y); bsw[6] = f2tf(rb1.z); bsw[7] = f2tf(rb1.w);
        }
        __syncthreads();
        buf ^= 1;
    }

    // Epilogue: c0,c1 @ (row g, cols 2t,2t+1); c2,c3 @ (row g+8)
#pragma unroll
    for (int mi = 0; mi < 4; mi++) {
#pragma unroll
        for (int ni = 0; ni < 4; ni++) {
            float* cp = C + (size_t)(bm + wm + mi * 16 + g) * ldc + wn + ni * 8 + 2 * t;
            *(float2*)cp              = make_float2(acc[mi][ni][0], acc[mi][ni][1]);
            *(float2*)(cp + 8 * ldc)  = make_float2(acc[mi][ni][2], acc[mi][ni][3]);
        }
    }
}

// Fused QKV projection: grid.x = 48 n-tiles (32 q | 8 k | 8 v), grid.y = 32 m-tiles
__global__ __launch_bounds__(256)
void qkv_gemm(const float* __restrict__ x, const float* __restrict__ wq,
              const float* __restrict__ wk, const float* __restrict__ wv,
              float* __restrict__ qkv) {
    const int bn = blockIdx.x;
    const float* B;
    if (bn < 32)      B = wq + (size_t)bn * 128 * HID;
    else if (bn < 40) B = wk + (size_t)(bn - 32) * 128 * HID;
    else              B = wv + (size_t)(bn - 40) * 128 * HID;
    gemm128(x, B, qkv + bn * 128, HID, HID, HID, QKV_LD, blockIdx.y * 128);
}

// Output projection: grid (32, 32)
__global__ __launch_bounds__(256)
void out_gemm(const float* __restrict__ A, const float* __restrict__ wo,
              float* __restrict__ C) {
    gemm128(A, wo + (size_t)blockIdx.x * 128 * HID, C + blockIdx.x * 128,
            HID, HID, HID, HID, blockIdx.y * 128);
}

// ---------------------------------------------------------------------------
// RoPE in-place on q (heads 0..31) and k (heads 32..39) of g_qkv.
// ---------------------------------------------------------------------------
__global__ void rope_kernel(float* __restrict__ qkv,
                            const int* __restrict__ positions) {
    int idx = blockIdx.x * blockDim.x + threadIdx.x;
    const int total = TOKENS * (NHEADS + NKVH) * 64;
    if (idx >= total) return;
    int d = idx & 63;
    int rest = idx >> 6;
    int head = rest % (NHEADS + NKVH);
    int t = rest / (NHEADS + NKVH);

    int pos = positions[t];
    pos = pos < 0 ? 0 : (pos > SEQ - 1 ? SEQ - 1 : pos);

    float* base = qkv + (size_t)t * QKV_LD +
                  (head < NHEADS ? head * HDIM : HID + (head - NHEADS) * HDIM);
    float x1 = base[d];
    float x2 = base[d + 64];

    const float LC = 0.14391156831212875f;   // ln(10000)/64
    int j1 = d >> 1;
    float f1 = expf(-(float)j1 * LC);
    float f2 = expf(-(float)(j1 + 32) * LC);
    float p = (float)pos;
    float s1, c1, s2, c2;
    sincosf(p * f1, &s1, &c1);
    sincosf(p * f2, &s2, &c2);

    base[d]      = x1 * c1 - x2 * s1;
    base[d + 64] = x2 * c2 + x1 * s2;
}

// ---------------------------------------------------------------------------
// Flash attention (fp32, causal, GQA) — unchanged from round 1.
// ---------------------------------------------------------------------------
#define ATT_SMEM ((3 * 64 * 128 + 64 * 65) * 4)

__device__ __forceinline__ int swz(int row, int k4) {
    return row * 32 + ((k4 & 24) | ((k4 ^ (row >> 2)) & 7));
}

__global__ __launch_bounds__(256)
void attn_kernel(const float* __restrict__ qkv, float* __restrict__ aout) {
    extern __shared__ float smem[];
    float4* Qs = (float4*)smem;
    float4* Ks = Qs + 64 * 32;
    float4* Vs = Ks + 64 * 32;
    float*  Ps = (float*)(Vs + 64 * 32);

    const int qb = blockIdx.x;
    const int h  = blockIdx.y;
    const int b  = blockIdx.z;
    const int kvh = h >> 2;
    const int tid = threadIdx.x;
    const int tx = tid & 15;
    const int ty = tid >> 4;
    const int q0 = qb * 64;
    const size_t tok0 = (size_t)b * SEQ;

    const float* qbase = qkv + (tok0 + q0) * QKV_LD + h * HDIM;
    for (int u = tid; u < 64 * 32; u += 256) {
        int r = u >> 5, k4 = u & 31;
        Qs[swz(r, k4)] = *(const float4*)(qbase + (size_t)r * QKV_LD + k4 * 4);
    }

    float m[4], l[4], o[4][8];
#pragma unroll
    for (int i = 0; i < 4; i++) {
        m[i] = -INFINITY; l[i] = 0.f;
#pragma unroll
        for (int j = 0; j < 8; j++) o[i][j] = 0.f;
    }

    const float* kbase = qkv + tok0 * QKV_LD + HID + kvh * HDIM;
    const float* vbase = kbase + NKVH * HDIM;

    for (int kb = 0; kb <= qb; kb++) {
        const int k0 = kb * 64;
        __syncthreads();
        for (int u = tid; u < 64 * 32; u += 256) {
            int r = u >> 5, k4 = u & 31;
            size_t roff = (size_t)(k0 + r) * QKV_LD + (size_t)k4 * 4;
            Ks[swz(r, k4)] = *(const float4*)(kbase + roff);
            Vs[u]          = *(const float4*)(vbase + roff);
        }
        __syncthreads();

        float s[4][4];
#pragma unroll
        for (int i = 0; i < 4; i++)
#pragma unroll
            for (int j = 0; j < 4; j++) s[i][j] = 0.f;

#pragma unroll 4
        for (int k4 = 0; k4 < 32; k4++) {
            float4 qv[4], kv[4];
#pragma unroll
            for (int i = 0; i < 4; i++)
                qv[i] = Qs[(ty * 4 + i) * 32 + ((k4 & 24) | ((k4 ^ ty) & 7))];
#pragma unroll
            for (int j = 0; j < 4; j++)
                kv[j] = Ks[(tx * 4 + j) * 32 + ((k4 & 24) | ((k4 ^ tx) & 7))];
#pragma unroll
            for (int i = 0; i < 4; i++)
#pragma unroll
                for (int j = 0; j < 4; j++)
                    s[i][j] += qv[i].x * kv[j].x + qv[i].y * kv[j].y +
                               qv[i].z * kv[j].z + qv[i].w * kv[j].w;
        }

        const float sc = 0.08838834764831845f;
#pragma unroll
        for (int i = 0; i < 4; i++) {
            const int qpos = q0 + ty * 4 + i;
            float rowm = -INFINITY;
#pragma unroll
            for (int j = 0; j < 4; j++) {
                float v = s[i][j] * sc;
                if (k0 + tx * 4 + j > qpos) v = -INFINITY;
                s[i][j] = v;
                rowm = fmaxf(rowm, v);
            }
#pragma unroll
            for (int off = 8; off; off >>= 1)
                rowm = fmaxf(rowm, __shfl_xor_sync(0xffffffffu, rowm, off));
            float nm = fmaxf(m[i], rowm);
            float corr = expf(m[i] - nm);
            float rs = 0.f;
#pragma unroll
            for (int j = 0; j < 4; j++) {
                float p = expf(s[i][j] - nm);
                Ps[(ty * 4 + i) * 65 + tx * 4 + j] = p;
                rs += p;
            }
#pragma unroll
            for (int off = 8; off; off >>= 1)
                rs += __shfl_xor_sync(0xffffffffu, rs, off);
            l[i] = l[i] * corr + rs;
            m[i] = nm;
#pragma unroll
            for (int j = 0; j < 8; j++) o[i][j] *= corr;
        }
        __syncthreads();

#pragma unroll 4
        for (int kk = 0; kk < 64; kk++) {
            float4 v1 = Vs[kk * 32 + tx];
            float4 v2 = Vs[kk * 32 + 16 + tx];
#pragma unroll
            for (int i = 0; i < 4; i++) {
                float p = Ps[(ty * 4 + i) * 65 + kk];
                o[i][0] += p * v1.x; o[i][1] += p * v1.y;
                o[i][2] += p * v1.z; o[i][3] += p * v1.w;
                o[i][4] += p * v2.x; o[i][5] += p * v2.y;
                o[i][6] += p * v2.z; o[i][7] += p * v2.w;
            }
        }
    }

    float* ob = aout + (tok0 + q0) * HID + h * HDIM;
#pragma unroll
    for (int i = 0; i < 4; i++) {
        int r = ty * 4 + i;
        float inv = 1.0f / l[i];
        float4 w1 = make_float4(o[i][0] * inv, o[i][1] * inv,
                                o[i][2] * inv, o[i][3] * inv);
        float4 w2 = make_float4(o[i][4] * inv, o[i][5] * inv,
                                o[i][6] * inv, o[i][7] * inv);
        *(float4*)(ob + (size_t)r * HID + tx * 4) = w1;
        *(float4*)(ob + (size_t)r * HID + 64 + tx * 4) = w2;
    }
}

// ---------------------------------------------------------------------------
// Launch
// ---------------------------------------------------------------------------
extern "C" void kernel_launch(void* const* d_in, const int* in_sizes, int n_in,
                              void* d_out, int out_size) {
    const float* x         = (const float*)d_in[0];
    const int*   positions = (const int*)d_in[1];
    const float* wq        = (const float*)d_in[3];
    const float* wk        = (const float*)d_in[4];
    const float* wv        = (const float*)d_in[5];
    const float* wo        = (const float*)d_in[6];
    float* out = (float*)d_out;

    float *qkv = nullptr, *attn = nullptr;
    cudaGetSymbolAddress((void**)&qkv, g_qkv);
    cudaGetSymbolAddress((void**)&attn, g_attn);

    // Fused QKV projection (tf32 tensor cores)
    qkv_gemm<<<dim3(48, 32), 256>>>(x, wq, wk, wv, qkv);

    // RoPE on q and k
    rope_kernel<<<(TOKENS * 40 * 64 + 255) / 256, 256>>>(qkv, positions);

    // Flash attention (fp32)
    cudaFuncSetAttribute(attn_kernel, cudaFuncAttributeMaxDynamicSharedMemorySize, ATT_SMEM);
    attn_kernel<<<dim3(SEQ / 64, NHEADS, TOKENS / SEQ), 256, ATT_SMEM>>>(qkv, attn);

    // Output projection (tf32 tensor cores)
    out_gemm<<<dim3(32, 32), 256>>>(attn, wo, out);
}

// round 4
// speedup vs baseline: 2.1750x; 1.0062x over previous
#include <cuda_runtime.h>
#include <math.h>
#include <stdint.h>

#define TOKENS 4096
#define HID    4096
#define NHEADS 32
#define NKVH   8
#define HDIM   128
#define SEQ    1024
#define QKV_LD 6144   // q(4096) | k(1024) | v(1024)

__device__ float g_qkv[TOKENS * QKV_LD];
__device__ float g_attn[TOKENS * HID];

// ---------------------------------------------------------------------------
// TF32 helpers (mma.sync path — tcgen05 unavailable: harness PTX target is
// plain sm_103, all tcgen05 features are 'a'-gated)
// ---------------------------------------------------------------------------
__device__ __forceinline__ unsigned f2tf(float x) {
    unsigned r;
    asm("cvt.rna.tf32.f32 %0, %1;" : "=r"(r) : "f"(x));
    return r;
}

__device__ __forceinline__ void mma_tf32(float c[4],
    unsigned a0, unsigned a1, unsigned a2, unsigned a3,
    unsigned b0, unsigned b1) {
    asm volatile(
        "mma.sync.aligned.m16n8k8.row.col.f32.tf32.tf32.f32 "
        "{%0,%1,%2,%3}, {%4,%5,%6,%7}, {%8,%9}, {%0,%1,%2,%3};"
        : "+f"(c[0]), "+f"(c[1]), "+f"(c[2]), "+f"(c[3])
        : "r"(a0), "r"(a1), "r"(a2), "r"(a3), "r"(b0), "r"(b1));
}

// ---------------------------------------------------------------------------
// TF32 GEMM: C[bm:bm+128, 0:256] = A[M,K] @ Bt[256,K]^T
// CTA tile 128x256, BK=16, 256 threads = 8 warps (2m x 4n), warp tile 64x64.
// Smem row stride 20 words: conflict-free STS and fragment gathers (measured
// in round 2). Double-buffered. 128 B smem traffic per mma -> tensor-bound.
// ---------------------------------------------------------------------------
#define SST   20
#define GSMEM ((2 * 128 * SST + 2 * 256 * SST) * 4)   // 60 KB

__device__ __forceinline__ void gemm256(
    const float* __restrict__ A, const float* __restrict__ Bt,
    float* __restrict__ C, int ldc, int bm)
{
    extern __shared__ unsigned smg[];
    unsigned* As0 = smg;                       // [2][128*SST]
    unsigned* Bs0 = smg + 2 * 128 * SST;       // [2][256*SST]

    const int tid  = threadIdx.x;
    const int lrow = tid >> 1;                 // 0..127
    const int lc8  = (tid & 1) * 8;            // 0 or 8
    const int wid  = tid >> 5;
    const int lane = tid & 31;
    const int g    = lane >> 2;
    const int t    = lane & 3;
    const int wm   = (wid & 1) * 64;
    const int wn   = (wid >> 1) * 64;

    const float* Ap  = A  + (size_t)(bm + lrow) * HID + lc8;
    const float* Bp0 = Bt + (size_t)lrow * HID + lc8;
    const float* Bp1 = Bt + (size_t)(lrow + 128) * HID + lc8;

    float acc[4][8][4];
#pragma unroll
    for (int i = 0; i < 4; i++)
#pragma unroll
        for (int j = 0; j < 8; j++)
#pragma unroll
            for (int r = 0; r < 4; r++) acc[i][j][r] = 0.f;

    float4 ra0, ra1, rb00, rb01, rb10, rb11;
    ra0  = *(const float4*)(Ap);      ra1  = *(const float4*)(Ap + 4);
    rb00 = *(const float4*)(Bp0);     rb01 = *(const float4*)(Bp0 + 4);
    rb10 = *(const float4*)(Bp1);     rb11 = *(const float4*)(Bp1 + 4);

#define STS_TILE(BUF) do { \
    unsigned* as = As0 + (BUF) * 128 * SST + lrow * SST + lc8; \
    as[0] = f2tf(ra0.x); as[1] = f2tf(ra0.y); as[2] = f2tf(ra0.z); as[3] = f2tf(ra0.w); \
    as[4] = f2tf(ra1.x); as[5] = f2tf(ra1.y); as[6] = f2tf(ra1.z); as[7] = f2tf(ra1.w); \
    unsigned* b0 = Bs0 + (BUF) * 256 * SST + lrow * SST + lc8; \
    b0[0] = f2tf(rb00.x); b0[1] = f2tf(rb00.y); b0[2] = f2tf(rb00.z); b0[3] = f2tf(rb00.w); \
    b0[4] = f2tf(rb01.x); b0[5] = f2tf(rb01.y); b0[6] = f2tf(rb01.z); b0[7] = f2tf(rb01.w); \
    unsigned* b1 = b0 + 128 * SST; \
    b1[0] = f2tf(rb10.x); b1[1] = f2tf(rb10.y); b1[2] = f2tf(rb10.z); b1[3] = f2tf(rb10.w); \
    b1[4] = f2tf(rb11.x); b1[5] = f2tf(rb11.y); b1[6] = f2tf(rb11.z); b1[7] = f2tf(rb11.w); \
} while (0)

    STS_TILE(0);
    __syncthreads();

    int buf = 0;
    for (int k0 = 0; k0 < HID; k0 += 16) {
        const bool nx = (k0 + 16) < HID;
        if (nx) {
            ra0  = *(const float4*)(Ap  + k0 + 16);
            ra1  = *(const float4*)(Ap  + k0 + 20);
            rb00 = *(const float4*)(Bp0 + k0 + 16);
            rb01 = *(const float4*)(Bp0 + k0 + 20);
            rb10 = *(const float4*)(Bp1 + k0 + 16);
            rb11 = *(const float4*)(Bp1 + k0 + 20);
        }

        const unsigned* as = As0 + buf * 128 * SST;
        const unsigned* bs = Bs0 + buf * 256 * SST;
#pragma unroll
        for (int ks = 0; ks < 2; ks++) {
            const int kb = ks * 8;
            unsigned af[4][4], bf[8][2];
#pragma unroll
            for (int mi = 0; mi < 4; mi++) {
                const unsigned* ap = as + (wm + mi * 16 + g) * SST + kb + t;
                af[mi][0] = ap[0];
                af[mi][1] = ap[8 * SST];
                af[mi][2] = ap[4];
                af[mi][3] = ap[8 * SST + 4];
            }
#pragma unroll
            for (int ni = 0; ni < 8; ni++) {
                const unsigned* bp = bs + (wn + ni * 8 + g) * SST + kb + t;
                bf[ni][0] = bp[0];
                bf[ni][1] = bp[4];
            }
#pragma unroll
            for (int mi = 0; mi < 4; mi++)
#pragma unroll
                for (int ni = 0; ni < 8; ni++)
                    mma_tf32(acc[mi][ni], af[mi][0], af[mi][1], af[mi][2], af[mi][3],
                             bf[ni][0], bf[ni][1]);
        }

        if (nx) STS_TILE(buf ^ 1);
        __syncthreads();
        buf ^= 1;
    }

    // Epilogue
#pragma unroll
    for (int mi = 0; mi < 4; mi++) {
#pragma unroll
        for (int ni = 0; ni < 8; ni++) {
            float* cp = C + (size_t)(bm + wm + mi * 16 + g) * ldc + wn + ni * 8 + 2 * t;
            *(float2*)cp             = make_float2(acc[mi][ni][0], acc[mi][ni][1]);
            *(float2*)(cp + 8 * ldc) = make_float2(acc[mi][ni][2], acc[mi][ni][3]);
        }
    }
#undef STS_TILE
}

// grid.x = 24 n-tiles (16 q | 4 k | 4 v), grid.y = 32 m-tiles
__global__ __launch_bounds__(256, 1)
void qkv_gemm(const float* __restrict__ x, const float* __restrict__ wq,
              const float* __restrict__ wk, const float* __restrict__ wv,
              float* __restrict__ qkv) {
    const int nt = blockIdx.x;
    const float* B;
    if (nt < 16)      B = wq + (size_t)nt * 256 * HID;
    else if (nt < 20) B = wk + (size_t)(nt - 16) * 256 * HID;
    else              B = wv + (size_t)(nt - 20) * 256 * HID;
    gemm256(x, B, qkv + nt * 256, QKV_LD, blockIdx.y * 128);
}

// grid.x = 16 n-tiles, grid.y = 32 m-tiles
__global__ __launch_bounds__(256, 1)
void out_gemm(const float* __restrict__ A, const float* __restrict__ wo,
              float* __restrict__ C) {
    gemm256(A, wo + (size_t)blockIdx.x * 256 * HID, C + blockIdx.x * 256,
            HID, blockIdx.y * 128);
}

// ---------------------------------------------------------------------------
// RoPE in-place on q (heads 0..31) and k (heads 32..39) of g_qkv.
// ---------------------------------------------------------------------------
__global__ void rope_kernel(float* __restrict__ qkv,
                            const int* __restrict__ positions) {
    int idx = blockIdx.x * blockDim.x + threadIdx.x;
    const int total = TOKENS * (NHEADS + NKVH) * 64;
    if (idx >= total) return;
    int d = idx & 63;
    int rest = idx >> 6;
    int head = rest % (NHEADS + NKVH);
    int t = rest / (NHEADS + NKVH);

    int pos = positions[t];
    pos = pos < 0 ? 0 : (pos > SEQ - 1 ? SEQ - 1 : pos);

    float* base = qkv + (size_t)t * QKV_LD +
                  (head < NHEADS ? head * HDIM : HID + (head - NHEADS) * HDIM);
    float x1 = base[d];
    float x2 = base[d + 64];

    const float LC = 0.14391156831212875f;   // ln(10000)/64
    int j1 = d >> 1;
    float f1 = expf(-(float)j1 * LC);
    float f2 = expf(-(float)(j1 + 32) * LC);
    float p = (float)pos;
    float s1, c1, s2, c2;
    sincosf(p * f1, &s1, &c1);
    sincosf(p * f2, &s2, &c2);

    base[d]      = x1 * c1 - x2 * s1;
    base[d + 64] = x2 * c2 + x1 * s2;
}

// ---------------------------------------------------------------------------
// Flash attention (fp32, causal, GQA) — unchanged (next round's target).
// ---------------------------------------------------------------------------
#define ATT_SMEM ((3 * 64 * 128 + 64 * 65) * 4)

__device__ __forceinline__ int swz(int row, int k4) {
    return row * 32 + ((k4 & 24) | ((k4 ^ (row >> 2)) & 7));
}

__global__ __launch_bounds__(256)
void attn_kernel(const float* __restrict__ qkv, float* __restrict__ aout) {
    extern __shared__ float smem[];
    float4* Qs = (float4*)smem;
    float4* Ks = Qs + 64 * 32;
    float4* Vs = Ks + 64 * 32;
    float*  Ps = (float*)(Vs + 64 * 32);

    const int qb = blockIdx.x;
    const int h  = blockIdx.y;
    const int b  = blockIdx.z;
    const int kvh = h >> 2;
    const int tid = threadIdx.x;
    const int tx = tid & 15;
    const int ty = tid >> 4;
    const int q0 = qb * 64;
    const size_t tok0 = (size_t)b * SEQ;

    const float* qbase = qkv + (tok0 + q0) * QKV_LD + h * HDIM;
    for (int u = tid; u < 64 * 32; u += 256) {
        int r = u >> 5, k4 = u & 31;
        Qs[swz(r, k4)] = *(const float4*)(qbase + (size_t)r * QKV_LD + k4 * 4);
    }

    float m[4], l[4], o[4][8];
#pragma unroll
    for (int i = 0; i < 4; i++) {
        m[i] = -INFINITY; l[i] = 0.f;
#pragma unroll
        for (int j = 0; j < 8; j++) o[i][j] = 0.f;
    }

    const float* kbase = qkv + tok0 * QKV_LD + HID + kvh * HDIM;
    const float* vbase = kbase + NKVH * HDIM;

    for (int kb = 0; kb <= qb; kb++) {
        const int k0 = kb * 64;
        __syncthreads();
        for (int u = tid; u < 64 * 32; u += 256) {
            int r = u >> 5, k4 = u & 31;
            size_t roff = (size_t)(k0 + r) * QKV_LD + (size_t)k4 * 4;
            Ks[swz(r, k4)] = *(const float4*)(kbase + roff);
            Vs[u]          = *(const float4*)(vbase + roff);
        }
        __syncthreads();

        float s[4][4];
#pragma unroll
        for (int i = 0; i < 4; i++)
#pragma unroll
            for (int j = 0; j < 4; j++) s[i][j] = 0.f;

#pragma unroll 4
        for (int k4 = 0; k4 < 32; k4++) {
            float4 qv[4], kv[4];
#pragma unroll
            for (int i = 0; i < 4; i++)
                qv[i] = Qs[(ty * 4 + i) * 32 + ((k4 & 24) | ((k4 ^ ty) & 7))];
#pragma unroll
            for (int j = 0; j < 4; j++)
                kv[j] = Ks[(tx * 4 + j) * 32 + ((k4 & 24) | ((k4 ^ tx) & 7))];
#pragma unroll
            for (int i = 0; i < 4; i++)
#pragma unroll
                for (int j = 0; j < 4; j++)
                    s[i][j] += qv[i].x * kv[j].x + qv[i].y * kv[j].y +
                               qv[i].z * kv[j].z + qv[i].w * kv[j].w;
        }

        const float sc = 0.08838834764831845f;
#pragma unroll
        for (int i = 0; i < 4; i++) {
            const int qpos = q0 + ty * 4 + i;
            float rowm = -INFINITY;
#pragma unroll
            for (int j = 0; j < 4; j++) {
                float v = s[i][j] * sc;
                if (k0 + tx * 4 + j > qpos) v = -INFINITY;
                s[i][j] = v;
                rowm = fmaxf(rowm, v);
            }
#pragma unroll
            for (int off = 8; off; off >>= 1)
                rowm = fmaxf(rowm, __shfl_xor_sync(0xffffffffu, rowm, off));
            float nm = fmaxf(m[i], rowm);
            float corr = expf(m[i] - nm);
            float rs = 0.f;
#pragma unroll
            for (int j = 0; j < 4; j++) {
                float p = expf(s[i][j] - nm);
                Ps[(ty * 4 + i) * 65 + tx * 4 + j] = p;
                rs += p;
            }
#pragma unroll
            for (int off = 8; off; off >>= 1)
                rs += __shfl_xor_sync(0xffffffffu, rs, off);
            l[i] = l[i] * corr + rs;
            m[i] = nm;
#pragma unroll
            for (int j = 0; j < 8; j++) o[i][j] *= corr;
        }
        __syncthreads();

#pragma unroll 4
        for (int kk = 0; kk < 64; kk++) {
            float4 v1 = Vs[kk * 32 + tx];
            float4 v2 = Vs[kk * 32 + 16 + tx];
#pragma unroll
            for (int i = 0; i < 4; i++) {
                float p = Ps[(ty * 4 + i) * 65 + kk];
                o[i][0] += p * v1.x; o[i][1] += p * v1.y;
                o[i][2] += p * v1.z; o[i][3] += p * v1.w;
                o[i][4] += p * v2.x; o[i][5] += p * v2.y;
                o[i][6] += p * v2.z; o[i][7] += p * v2.w;
            }
        }
    }

    float* ob = aout + (tok0 + q0) * HID + h * HDIM;
#pragma unroll
    for (int i = 0; i < 4; i++) {
        int r = ty * 4 + i;
        float inv = 1.0f / l[i];
        float4 w1 = make_float4(o[i][0] * inv, o[i][1] * inv,
                                o[i][2] * inv, o[i][3] * inv);
        float4 w2 = make_float4(o[i][4] * inv, o[i][5] * inv,
                                o[i][6] * inv, o[i][7] * inv);
        *(float4*)(ob + (size_t)r * HID + tx * 4) = w1;
        *(float4*)(ob + (size_t)r * HID + 64 + tx * 4) = w2;
    }
}

// ---------------------------------------------------------------------------
// Launch
// ---------------------------------------------------------------------------
extern "C" void kernel_launch(void* const* d_in, const int* in_sizes, int n_in,
                              void* d_out, int out_size) {
    const float* x         = (const float*)d_in[0];
    const int*   positions = (const int*)d_in[1];
    const float* wq        = (const float*)d_in[3];
    const float* wk        = (const float*)d_in[4];
    const float* wv        = (const float*)d_in[5];
    const float* wo        = (const float*)d_in[6];
    float* out = (float*)d_out;

    float *qkv = nullptr, *attn = nullptr;
    cudaGetSymbolAddress((void**)&qkv, g_qkv);
    cudaGetSymbolAddress((void**)&attn, g_attn);

    cudaFuncSetAttribute(qkv_gemm, cudaFuncAttributeMaxDynamicSharedMemorySize, GSMEM);
    cudaFuncSetAttribute(out_gemm, cudaFuncAttributeMaxDynamicSharedMemorySize, GSMEM);
    cudaFuncSetAttribute(attn_kernel, cudaFuncAttributeMaxDynamicSharedMemorySize, ATT_SMEM);

    // QKV projection (tf32 HMMA, 128x256 tiles)
    qkv_gemm<<<dim3(24, 32), 256, GSMEM>>>(x, wq, wk, wv, qkv);

    // RoPE on q and k
    rope_kernel<<<(TOKENS * 40 * 64 + 255) / 256, 256>>>(qkv, positions);

    // Flash attention (fp32)
    attn_kernel<<<dim3(SEQ / 64, NHEADS, TOKENS / SEQ), 256, ATT_SMEM>>>(qkv, attn);

    // Output projection (tf32 HMMA, 128x256 tiles)
    out_gemm<<<dim3(16, 32), 256, GSMEM>>>(attn, wo, out);
}

// round 5
// speedup vs baseline: 2.5101x; 1.1541x over previous
#include <cuda_runtime.h>
#include <math.h>
#include <stdint.h>

#define TOKENS 4096
#define HID    4096
#define NHEADS 32
#define NKVH   8
#define HDIM   128
#define SEQ    1024
#define QKV_LD 6144   // q(4096) | k(1024) | v(1024)

__device__ float g_qkv[TOKENS * QKV_LD];
__device__ float g_attn[TOKENS * HID];

// ---------------------------------------------------------------------------
// Helpers (mma.sync path — tcgen05 unavailable: harness PTX target is plain
// sm_103; all tcgen05 features are 'a'-gated)
// ---------------------------------------------------------------------------
__device__ __forceinline__ uint32_t smem_u32(const void* p) {
    uint32_t a;
    asm("{ .reg .u64 t; cvta.to.shared.u64 t, %1; cvt.u32.u64 %0, t; }"
        : "=r"(a) : "l"(p));
    return a;
}
__device__ __forceinline__ unsigned f2tf(float x) {
    unsigned r;
    asm("cvt.rna.tf32.f32 %0, %1;" : "=r"(r) : "f"(x));
    return r;
}
__device__ __forceinline__ void mma_tf32(float c[4],
    unsigned a0, unsigned a1, unsigned a2, unsigned a3,
    unsigned b0, unsigned b1) {
    asm volatile(
        "mma.sync.aligned.m16n8k8.row.col.f32.tf32.tf32.f32 "
        "{%0,%1,%2,%3}, {%4,%5,%6,%7}, {%8,%9}, {%0,%1,%2,%3};"
        : "+f"(c[0]), "+f"(c[1]), "+f"(c[2]), "+f"(c[3])
        : "r"(a0), "r"(a1), "r"(a2), "r"(a3), "r"(b0), "r"(b1));
}
__device__ __forceinline__ void cp16(uint32_t d, const void* s) {
    asm volatile("cp.async.cg.shared.global [%0], [%1], 16;" :: "r"(d), "l"(s));
}
#define CP_COMMIT() asm volatile("cp.async.commit_group;" ::: "memory")
#define CP_WAIT2()  asm volatile("cp.async.wait_group 2;" ::: "memory")

// ---------------------------------------------------------------------------
// TF32 GEMM: C[bm:bm+128, 0:256] = A[M,K] @ Bt[256,K]^T
// CTA 128x256, BK=16, 256 threads = 8 warps (2m x 4n), warp tile 64x64.
// 4-stage cp.async pipeline (raw fp32 in smem, cvt.rna.tf32 at gather).
// Smem row stride 20 words: conflict-free gathers (proven rounds 2/4).
// ---------------------------------------------------------------------------
#define SST   20
#define ASTG  (128 * SST)                 // words per A stage
#define BSTG  (256 * SST)                 // words per B stage
#define STGW  (ASTG + BSTG)               // 7680 words = 30 KB
#define NST   4
#define KT    (HID / 16)                  // 256 iters
#define GSMEM (NST * STGW * 4)            // 120 KB

__device__ __forceinline__ void gemm256(
    const float* __restrict__ A, const float* __restrict__ Bt,
    float* __restrict__ C, int ldc, int bm)
{
    extern __shared__ float smg[];

    const int tid  = threadIdx.x;
    const int wid  = tid >> 5;
    const int lane = tid & 31;
    const int g    = lane >> 2;
    const int t    = lane & 3;
    const int wm   = (wid & 1) * 64;
    const int wn   = (wid >> 1) * 64;
    const int lr   = tid >> 2;            // 0..63 load row base
    const int lc   = (tid & 3) * 4;       // k-chunk (floats)

    const uint32_t sb   = smem_u32(smg);
    const uint32_t adst = sb + (uint32_t)(lr * SST + lc) * 4u;
    const uint32_t bdst = adst + ASTG * 4u;

    const float* asrc = A  + (size_t)(bm + lr) * HID + lc;
    const float* bsrc = Bt + (size_t)lr * HID + lc;

#define ISSUE(S, KI) do { \
    const float* a_ = asrc + (KI) * 16; \
    const float* b_ = bsrc + (KI) * 16; \
    const uint32_t so_ = (uint32_t)(S) * (STGW * 4u); \
    cp16(adst + so_,                  a_); \
    cp16(adst + so_ + 64u*SST*4u,     a_ + (size_t)64 * HID); \
    cp16(bdst + so_,                  b_); \
    cp16(bdst + so_ + 64u*SST*4u,     b_ + (size_t)64 * HID); \
    cp16(bdst + so_ + 128u*SST*4u,    b_ + (size_t)128 * HID); \
    cp16(bdst + so_ + 192u*SST*4u,    b_ + (size_t)192 * HID); \
} while (0)

    float acc[4][8][4];
#pragma unroll
    for (int i = 0; i < 4; i++)
#pragma unroll
        for (int j = 0; j < 8; j++)
#pragma unroll
            for (int r = 0; r < 4; r++) acc[i][j][r] = 0.f;

    // Prologue: fill 3 stages
    ISSUE(0, 0); CP_COMMIT();
    ISSUE(1, 1); CP_COMMIT();
    ISSUE(2, 2); CP_COMMIT();

    for (int i = 0; i < KT; i++) {
        CP_WAIT2();            // stage i's group complete (this thread)
        __syncthreads();       // all threads' cp.asyncs for stage i visible

        if (i + 3 < KT) ISSUE((i + 3) & 3, i + 3);
        CP_COMMIT();           // one group per iter keeps wait counting uniform

        const float* as = smg + (i & 3) * STGW;
        const float* bs = as + ASTG;
#pragma unroll
        for (int ks = 0; ks < 2; ks++) {
            const int kb = ks * 8;
            unsigned af[4][4], bf[8][2];
#pragma unroll
            for (int mi = 0; mi < 4; mi++) {
                const float* ap = as + (wm + mi * 16 + g) * SST + kb + t;
                af[mi][0] = f2tf(ap[0]);
                af[mi][1] = f2tf(ap[8 * SST]);
                af[mi][2] = f2tf(ap[4]);
                af[mi][3] = f2tf(ap[8 * SST + 4]);
            }
#pragma unroll
            for (int ni = 0; ni < 8; ni++) {
                const float* bp = bs + (wn + ni * 8 + g) * SST + kb + t;
                bf[ni][0] = f2tf(bp[0]);
                bf[ni][1] = f2tf(bp[4]);
            }
#pragma unroll
            for (int mi = 0; mi < 4; mi++)
#pragma unroll
                for (int ni = 0; ni < 8; ni++)
                    mma_tf32(acc[mi][ni], af[mi][0], af[mi][1], af[mi][2], af[mi][3],
                             bf[ni][0], bf[ni][1]);
        }
    }
#undef ISSUE

    // Epilogue
#pragma unroll
    for (int mi = 0; mi < 4; mi++) {
#pragma unroll
        for (int ni = 0; ni < 8; ni++) {
            float* cp = C + (size_t)(bm + wm + mi * 16 + g) * ldc + wn + ni * 8 + 2 * t;
            *(float2*)cp             = make_float2(acc[mi][ni][0], acc[mi][ni][1]);
            *(float2*)(cp + 8 * ldc) = make_float2(acc[mi][ni][2], acc[mi][ni][3]);
        }
    }
}

// grid.x = 24 n-tiles (16 q | 4 k | 4 v), grid.y = 32 m-tiles
__global__ __launch_bounds__(256, 1)
void qkv_gemm(const float* __restrict__ x, const float* __restrict__ wq,
              const float* __restrict__ wk, const float* __restrict__ wv,
              float* __restrict__ qkv) {
    const int nt = blockIdx.x;
    const float* B;
    if (nt < 16)      B = wq + (size_t)nt * 256 * HID;
    else if (nt < 20) B = wk + (size_t)(nt - 16) * 256 * HID;
    else              B = wv + (size_t)(nt - 20) * 256 * HID;
    gemm256(x, B, qkv + nt * 256, QKV_LD, blockIdx.y * 128);
}

// grid.x = 16 n-tiles, grid.y = 32 m-tiles
__global__ __launch_bounds__(256, 1)
void out_gemm(const float* __restrict__ A, const float* __restrict__ wo,
              float* __restrict__ C) {
    gemm256(A, wo + (size_t)blockIdx.x * 256 * HID, C + blockIdx.x * 256,
            HID, blockIdx.y * 128);
}

// ---------------------------------------------------------------------------
// RoPE in-place on q (heads 0..31) and k (heads 32..39) of g_qkv.
// ---------------------------------------------------------------------------
__global__ void rope_kernel(float* __restrict__ qkv,
                            const int* __restrict__ positions) {
    int idx = blockIdx.x * blockDim.x + threadIdx.x;
    const int total = TOKENS * (NHEADS + NKVH) * 64;
    if (idx >= total) return;
    int d = idx & 63;
    int rest = idx >> 6;
    int head = rest % (NHEADS + NKVH);
    int t = rest / (NHEADS + NKVH);

    int pos = positions[t];
    pos = pos < 0 ? 0 : (pos > SEQ - 1 ? SEQ - 1 : pos);

    float* base = qkv + (size_t)t * QKV_LD +
                  (head < NHEADS ? head * HDIM : HID + (head - NHEADS) * HDIM);
    float x1 = base[d];
    float x2 = base[d + 64];

    const float LC = 0.14391156831212875f;   // ln(10000)/64
    int j1 = d >> 1;
    float f1 = expf(-(float)j1 * LC);
    float f2 = expf(-(float)(j1 + 32) * LC);
    float p = (float)pos;
    float s1, c1, s2, c2;
    sincosf(p * f1, &s1, &c1);
    sincosf(p * f2, &s2, &c2);

    base[d]      = x1 * c1 - x2 * s1;
    base[d + 64] = x2 * c2 + x1 * s2;
}

// ---------------------------------------------------------------------------
// Flash attention (fp32, causal, GQA) — unchanged (next round's target).
// ---------------------------------------------------------------------------
#define ATT_SMEM ((3 * 64 * 128 + 64 * 65) * 4)

__device__ __forceinline__ int swz(int row, int k4) {
    return row * 32 + ((k4 & 24) | ((k4 ^ (row >> 2)) & 7));
}

__global__ __launch_bounds__(256)
void attn_kernel(const float* __restrict__ qkv, float* __restrict__ aout) {
    extern __shared__ float smem[];
    float4* Qs = (float4*)smem;
    float4* Ks = Qs + 64 * 32;
    float4* Vs = Ks + 64 * 32;
    float*  Ps = (float*)(Vs + 64 * 32);

    const int qb = blockIdx.x;
    const int h  = blockIdx.y;
    const int b  = blockIdx.z;
    const int kvh = h >> 2;
    const int tid = threadIdx.x;
    const int tx = tid & 15;
    const int ty = tid >> 4;
    const int q0 = qb * 64;
    const size_t tok0 = (size_t)b * SEQ;

    const float* qbase = qkv + (tok0 + q0) * QKV_LD + h * HDIM;
    for (int u = tid; u < 64 * 32; u += 256) {
        int r = u >> 5, k4 = u & 31;
        Qs[swz(r, k4)] = *(const float4*)(qbase + (size_t)r * QKV_LD + k4 * 4);
    }

    float m[4], l[4], o[4][8];
#pragma unroll
    for (int i = 0; i < 4; i++) {
        m[i] = -INFINITY; l[i] = 0.f;
#pragma unroll
        for (int j = 0; j < 8; j++) o[i][j] = 0.f;
    }

    const float* kbase = qkv + tok0 * QKV_LD + HID + kvh * HDIM;
    const float* vbase = kbase + NKVH * HDIM;

    for (int kb = 0; kb <= qb; kb++) {
        const int k0 = kb * 64;
        __syncthreads();
        for (int u = tid; u < 64 * 32; u += 256) {
            int r = u >> 5, k4 = u & 31;
            size_t roff = (size_t)(k0 + r) * QKV_LD + (size_t)k4 * 4;
            Ks[swz(r, k4)] = *(const float4*)(kbase + roff);
            Vs[u]          = *(const float4*)(vbase + roff);
        }
        __syncthreads();

        float s[4][4];
#pragma unroll
        for (int i = 0; i < 4; i++)
#pragma unroll
            for (int j = 0; j < 4; j++) s[i][j] = 0.f;

#pragma unroll 4
        for (int k4 = 0; k4 < 32; k4++) {
            float4 qv[4], kv[4];
#pragma unroll
            for (int i = 0; i < 4; i++)
                qv[i] = Qs[(ty * 4 + i) * 32 + ((k4 & 24) | ((k4 ^ ty) & 7))];
#pragma unroll
            for (int j = 0; j < 4; j++)
                kv[j] = Ks[(tx * 4 + j) * 32 + ((k4 & 24) | ((k4 ^ tx) & 7))];
#pragma unroll
            for (int i = 0; i < 4; i++)
#pragma unroll
                for (int j = 0; j < 4; j++)
                    s[i][j] += qv[i].x * kv[j].x + qv[i].y * kv[j].y +
                               qv[i].z * kv[j].z + qv[i].w * kv[j].w;
        }

        const float sc = 0.08838834764831845f;
#pragma unroll
        for (int i = 0; i < 4; i++) {
            const int qpos = q0 + ty * 4 + i;
            float rowm = -INFINITY;
#pragma unroll
            for (int j = 0; j < 4; j++) {
                float v = s[i][j] * sc;
                if (k0 + tx * 4 + j > qpos) v = -INFINITY;
                s[i][j] = v;
                rowm = fmaxf(rowm, v);
            }
#pragma unroll
            for (int off = 8; off; off >>= 1)
                rowm = fmaxf(rowm, __shfl_xor_sync(0xffffffffu, rowm, off));
            float nm = fmaxf(m[i], rowm);
            float corr = expf(m[i] - nm);
            float rs = 0.f;
#pragma unroll
            for (int j = 0; j < 4; j++) {
                float p = expf(s[i][j] - nm);
                Ps[(ty * 4 + i) * 65 + tx * 4 + j] = p;
                rs += p;
            }
#pragma unroll
            for (int off = 8; off; off >>= 1)
                rs += __shfl_xor_sync(0xffffffffu, rs, off);
            l[i] = l[i] * corr + rs;
            m[i] = nm;
#pragma unroll
            for (int j = 0; j < 8; j++) o[i][j] *= corr;
        }
        __syncthreads();

#pragma unroll 4
        for (int kk = 0; kk < 64; kk++) {
            float4 v1 = Vs[kk * 32 + tx];
            float4 v2 = Vs[kk * 32 + 16 + tx];
#pragma unroll
            for (int i = 0; i < 4; i++) {
                float p = Ps[(ty * 4 + i) * 65 + kk];
                o[i][0] += p * v1.x; o[i][1] += p * v1.y;
                o[i][2] += p * v1.z; o[i][3] += p * v1.w;
                o[i][4] += p * v2.x; o[i][5] += p * v2.y;
                o[i][6] += p * v2.z; o[i][7] += p * v2.w;
            }
        }
    }

    float* ob = aout + (tok0 + q0) * HID + h * HDIM;
#pragma unroll
    for (int i = 0; i < 4; i++) {
        int r = ty * 4 + i;
        float inv = 1.0f / l[i];
        float4 w1 = make_float4(o[i][0] * inv, o[i][1] * inv,
                                o[i][2] * inv, o[i][3] * inv);
        float4 w2 = make_float4(o[i][4] * inv, o[i][5] * inv,
                                o[i][6] * inv, o[i][7] * inv);
        *(float4*)(ob + (size_t)r * HID + tx * 4) = w1;
        *(float4*)(ob + (size_t)r * HID + 64 + tx * 4) = w2;
    }
}

// ---------------------------------------------------------------------------
// Launch
// ---------------------------------------------------------------------------
extern "C" void kernel_launch(void* const* d_in, const int* in_sizes, int n_in,
                              void* d_out, int out_size) {
    const float* x         = (const float*)d_in[0];
    const int*   positions = (const int*)d_in[1];
    const float* wq        = (const float*)d_in[3];
    const float* wk        = (const float*)d_in[4];
    const float* wv        = (const float*)d_in[5];
    const float* wo        = (const float*)d_in[6];
    float* out = (float*)d_out;

    float *qkv = nullptr, *attn = nullptr;
    cudaGetSymbolAddress((void**)&qkv, g_qkv);
    cudaGetSymbolAddress((void**)&attn, g_attn);

    cudaFuncSetAttribute(qkv_gemm, cudaFuncAttributeMaxDynamicSharedMemorySize, GSMEM);
    cudaFuncSetAttribute(out_gemm, cudaFuncAttributeMaxDynamicSharedMemorySize, GSMEM);
    cudaFuncSetAttribute(attn_kernel, cudaFuncAttributeMaxDynamicSharedMemorySize, ATT_SMEM);

    // QKV projection (tf32 HMMA, cp.async 4-stage pipeline)
    qkv_gemm<<<dim3(24, 32), 256, GSMEM>>>(x, wq, wk, wv, qkv);

    // RoPE on q and k
    rope_kernel<<<(TOKENS * 40 * 64 + 255) / 256, 256>>>(qkv, positions);

    // Flash attention (fp32)
    attn_kernel<<<dim3(SEQ / 64, NHEADS, TOKENS / SEQ), 256, ATT_SMEM>>>(qkv, attn);

    // Output projection (tf32 HMMA, cp.async 4-stage pipeline)
    out_gemm<<<dim3(16, 32), 256, GSMEM>>>(attn, wo, out);
}